// round 16
// baseline (speedup 1.0000x reference)
#include <cuda_runtime.h>
#include <cuda_fp16.h>
#include <cstdint>

#define BATCH 32
#define NNODE 128
#define EDGES (NNODE * (NNODE - 1))

typedef unsigned long long ull;
typedef uint32_t u32;

// ---------------- static device scratch ----------------
__device__ float g_W1t[128 * 256];            // W1t[i*256+o] = W1[o,i]
__device__ uint4 g_Bp[16 * 4 * 32];           // W2 B-frags PAIRED: [kstep][ntile-pair][lane]
__device__ uint2 g_O1f[4 * 32 * 32];          // O1  B-frags (K=64,  N=256)
__device__ uint2 g_O2f[16 * 32 * 32];         // O2  B-frags (K=256, N=256)
__device__ uint2 g_O3f[16 * 8 * 32];          // O3  B-frags (K=256, N=64)
__device__ u32 g_H1s16[BATCH * NNODE * 128];  // fp16x2 sender-half
__device__ u32 g_H1r16[BATCH * NNODE * 128];  // fp16x2 recv-half (+b1)
__device__ float g_AGG[BATCH * NNODE * 64];

// ---------------- helpers ----------------
__device__ __forceinline__ u32 smem_u32(const void* p) {
    u32 a;
    asm("{ .reg .u64 t; cvta.to.shared.u64 t, %1; cvt.u32.u64 %0, t; }" : "=r"(a) : "l"(p));
    return a;
}
__device__ __forceinline__ u32 pk_h2(float hi_val, float lo_val) {
    u32 d; asm("cvt.rn.f16x2.f32 %0, %1, %2;" : "=r"(d) : "f"(hi_val), "f"(lo_val));
    return d;
}
__device__ __forceinline__ u32 frelu2(u32 hs, u32 hr) {
    u32 d;
    asm("fma.rn.relu.f16x2 %0, %1, %2, %3;" : "=r"(d) : "r"(hs), "r"(0x3C003C00u), "r"(hr));
    return d;
}
__device__ __forceinline__ void ldmatrix_x4(u32& a0, u32& a1, u32& a2, u32& a3, u32 addr) {
    asm volatile("ldmatrix.sync.aligned.m8n8.x4.shared.b16 {%0,%1,%2,%3}, [%4];"
                 : "=r"(a0), "=r"(a1), "=r"(a2), "=r"(a3) : "r"(addr));
}
__device__ __forceinline__ void hmma(float* c, u32 a0, u32 a1, u32 a2, u32 a3, u32 b0, u32 b1) {
    asm volatile(
        "mma.sync.aligned.m16n8k16.row.col.f32.f16.f16.f32 "
        "{%0,%1,%2,%3}, {%4,%5,%6,%7}, {%8,%9}, {%0,%1,%2,%3};"
        : "+f"(c[0]), "+f"(c[1]), "+f"(c[2]), "+f"(c[3])
        : "r"(a0), "r"(a1), "r"(a2), "r"(a3), "r"(b0), "r"(b1));
}
// build one B-fragment uint2 for row-major weight W[N][K]
__device__ __forceinline__ uint2 mk_bfrag(const float* W, int K, int t, int nt, int l) {
    int k0 = t * 16 + (l & 3) * 2;
    int col = nt * 8 + (l >> 2);
    __half h0 = __float2half_rn(W[col * K + k0]);
    __half h1 = __float2half_rn(W[col * K + k0 + 1]);
    __half h8 = __float2half_rn(W[col * K + k0 + 8]);
    __half h9 = __float2half_rn(W[col * K + k0 + 9]);
    uint2 o;
    o.x = (u32)__half_as_ushort(h0) | ((u32)__half_as_ushort(h1) << 16);
    o.y = (u32)__half_as_ushort(h8) | ((u32)__half_as_ushort(h9) << 16);
    return o;
}

// ---------------- prep: W1 transpose + all mma B-fragments ----------------
__global__ void prep_kernel(const float* __restrict__ W1, const float* __restrict__ W2,
                            const float* __restrict__ O1, const float* __restrict__ O2,
                            const float* __restrict__ O3) {
    const int total = 32768 + 2048 + 4096 + 16384 + 4096;
    for (int t0 = blockIdx.x * blockDim.x + threadIdx.x; t0 < total;
         t0 += gridDim.x * blockDim.x) {
        int x = t0;
        if (x < 32768) {
            int i = x >> 8, o = x & 255;
            g_W1t[x] = W1[o * 128 + i];
        } else if ((x -= 32768) < 2048) {      // W2 paired frags: 16 ksteps x 4 pairs
            int t = x >> 7, np = (x >> 5) & 3, l = x & 31;
            uint2 e0 = mk_bfrag(W2, 256, t, 2 * np, l);
            uint2 e1 = mk_bfrag(W2, 256, t, 2 * np + 1, l);
            g_Bp[x] = make_uint4(e0.x, e0.y, e1.x, e1.y);
        } else if ((x -= 2048) < 4096) {       // O1 frags: 4 ksteps x 32 ntiles
            int t = x >> 10, nt = (x >> 5) & 31, l = x & 31;
            g_O1f[x] = mk_bfrag(O1, 64, t, nt, l);
        } else if ((x -= 4096) < 16384) {      // O2 frags: 16 x 32
            int t = x >> 10, nt = (x >> 5) & 31, l = x & 31;
            g_O2f[x] = mk_bfrag(O2, 256, t, nt, l);
        } else {                               // O3 frags: 16 x 8
            x -= 16384;
            int t = x >> 8, nt = (x >> 5) & 7, l = x & 31;
            g_O3f[x] = mk_bfrag(O3, 256, t, nt, l);
        }
    }
}

// ---------------- h1: per-node layer-1 halves -> fp16x2 ----------------
__global__ void __launch_bounds__(256) h1_kernel(const float* __restrict__ inp,
                                                 const float* __restrict__ b1) {
    const int row = blockIdx.x;
    const int tid = threadIdx.x;
    const int u = tid & 127, half = tid >> 7;
    __shared__ float xs[64];
    if (tid < 64) xs[tid] = inp[row * 64 + tid];
    __syncthreads();
    float v0 = half ? b1[2 * u] : 0.f;
    float v1 = half ? b1[2 * u + 1] : 0.f;
    const float* wb = &g_W1t[half * 64 * 256 + 2 * u];
#pragma unroll 8
    for (int i = 0; i < 64; ++i) {
        float2 w = *(const float2*)(wb + i * 256);
        float x = xs[i];
        v0 = fmaf(x, w.x, v0);
        v1 = fmaf(x, w.y, v1);
    }
    u32 p = pk_h2(v1, v0);
    if (half) g_H1r16[row * 128 + u] = p;
    else      g_H1s16[row * 128 + u] = p;
}

// ---------------- edge kernel: 2 receivers/CTA, shared-sender staging ----------------
// CTA per (b, pair p): receivers r0=2p, r1=2p+1. 16 warps: rv=w>>3 receiver,
// rows 16(w&7)..+15. Sender rows identical for both receivers except e==r0,
// so warp pair (g, g+8) stages both tiles from ONE H1s load per row-part.
// Each lane covers a full 512B row-part range: part = lane64&31 (32 x 16B).
#define A_STRIDE 528
#define OFF_T0 0                 // 128*528 = 67584
#define OFF_T1 67584
#define OFF_RED 135168           // 2 x 8 x 68 floats = 4352
#define SMEM_EDGE 139520

__global__ void __launch_bounds__(512, 1) edge_kernel(const float* __restrict__ rt,
                                                      const float* __restrict__ b2) {
    extern __shared__ unsigned char sm[];
    const u32 smb = smem_u32(sm);
    const int p = blockIdx.x & 63, b = blockIdx.x >> 6;
    const int r0 = 2 * p;
    const int tid = threadIdx.x, w = tid >> 5, l = tid & 31;
    const int g = w & 7, rv = w >> 3;
    const int r = r0 + rv;
    float* red = (float*)(sm + OFF_RED);

    // rt weights for own receiver's edges: lane l<16 holds edge g*16+l
    float rtv = 0.f;
    {
        int e0 = g * 16 + l;
        if (l < 16 && e0 < 127) {
            const float* q = rt + ((size_t)(b * EDGES + r * 127 + e0)) * 2;
            rtv = q[0] + q[1];
        }
    }

    const u32* h1s = &g_H1s16[b * NNODE * 128];

    // ---- cooperative pair staging: warps g and g+8 stage rows g*16..+15 of BOTH tiles ----
    {
        const int lane64 = rv * 32 + l;
        const int part = lane64 & 31;                   // 32 parts x 16B = full 512B row
        const int rowoff = lane64 >> 5;                 // warp g: even rows, warp g+8: odd rows
        uint4 hr0 = *(const uint4*)&g_H1r16[(b * NNODE + r0) * 128 + part * 4];
        uint4 hr1 = *(const uint4*)&g_H1r16[(b * NNODE + r0 + 1) * 128 + part * 4];
#pragma unroll
        for (int i = 0; i < 8; ++i) {
            int e = g * 16 + i * 2 + rowoff;
            uint4 v0 = make_uint4(0u, 0u, 0u, 0u), v1 = v0;
            if (e < 127) {
                int s0 = e + (e >= r0);
                uint4 hs = *(const uint4*)&h1s[s0 * 128 + part * 4];
                v0.x = frelu2(hs.x, hr0.x);
                v0.y = frelu2(hs.y, hr0.y);
                v0.z = frelu2(hs.z, hr0.z);
                v0.w = frelu2(hs.w, hr0.w);
                if (e == r0)                            // s1 = r0 differs from s0 here
                    hs = *(const uint4*)&h1s[r0 * 128 + part * 4];
                v1.x = frelu2(hs.x, hr1.x);
                v1.y = frelu2(hs.y, hr1.y);
                v1.z = frelu2(hs.z, hr1.z);
                v1.w = frelu2(hs.w, hr1.w);
            }
            *(uint4*)(sm + OFF_T0 + e * A_STRIDE + part * 16) = v0;
            *(uint4*)(sm + OFF_T1 + e * A_STRIDE + part * 16) = v1;
        }
    }
    asm volatile("bar.sync %0, 64;" :: "r"(g + 1) : "memory");

    // ---- mma: 16 k-steps x 8 n-tiles, B pairs prefetched one k-step ahead ----
    float c[8][4];
#pragma unroll
    for (int n = 0; n < 8; ++n)
#pragma unroll
        for (int q = 0; q < 4; ++q) c[n][q] = 0.f;

    const u32 arow = smb + (rv ? OFF_T1 : OFF_T0) + (g * 16 + (l & 15)) * A_STRIDE + (l >> 4) * 16;
    uint4 Bp[4];
#pragma unroll
    for (int np = 0; np < 4; ++np) Bp[np] = __ldg(&g_Bp[np * 32 + l]);
#pragma unroll
    for (int t = 0; t < 16; ++t) {
        u32 a0, a1, a2, a3;
        ldmatrix_x4(a0, a1, a2, a3, arow + t * 32);
        uint4 Bn[4];
        if (t < 15) {
#pragma unroll
            for (int np = 0; np < 4; ++np)
                Bn[np] = __ldg(&g_Bp[((t + 1) * 4 + np) * 32 + l]);
        }
#pragma unroll
        for (int np = 0; np < 4; ++np) {
            hmma(c[2 * np], a0, a1, a2, a3, Bp[np].x, Bp[np].y);
            hmma(c[2 * np + 1], a0, a1, a2, a3, Bp[np].z, Bp[np].w);
        }
#pragma unroll
        for (int np = 0; np < 4; ++np) Bp[np] = Bn[np];
    }

    // ---- epilogue: relu(C+b2)*rt, reduce over this warp's 16 edges ----
    float rt0 = __shfl_sync(0xffffffffu, rtv, l >> 2);
    float rt1 = __shfl_sync(0xffffffffu, rtv, 8 + (l >> 2));
#pragma unroll
    for (int n = 0; n < 8; ++n) {
        int n0 = n * 8 + (l & 3) * 2;
        float bb0 = __ldg(&b2[n0]), bb1 = __ldg(&b2[n0 + 1]);
        float u0 = fmaxf(c[n][0] + bb0, 0.f) * rt0 + fmaxf(c[n][2] + bb0, 0.f) * rt1;
        float u1 = fmaxf(c[n][1] + bb1, 0.f) * rt0 + fmaxf(c[n][3] + bb1, 0.f) * rt1;
#pragma unroll
        for (int off = 4; off < 32; off <<= 1) {
            u0 += __shfl_xor_sync(0xffffffffu, u0, off);
            u1 += __shfl_xor_sync(0xffffffffu, u1, off);
        }
        if (l < 4) {
            red[rv * 544 + g * 68 + n0] = u0;
            red[rv * 544 + g * 68 + n0 + 1] = u1;
        }
    }
    __syncthreads();
    if (tid < 128) {
        int rv2 = tid >> 6, col = tid & 63;
        float a = 0.f;
#pragma unroll
        for (int ww = 0; ww < 8; ++ww) a += red[rv2 * 544 + ww * 68 + col];
        g_AGG[(b * NNODE + r0 + rv2) * 64 + col] = a;
    }
}

// ---------------- node kernel: HMMA MLP 64 -> 256 -> 256 -> 64 ----------------
#define N_STRIDE 528
#define NOFF_A0 0
#define NOFF_A1 8448
#define SMEM_NODE 16896

__global__ void __launch_bounds__(256) node_kernel(const float* __restrict__ o1b,
                                                   const float* __restrict__ o2b,
                                                   const float* __restrict__ o3b,
                                                   float* __restrict__ out) {
    extern __shared__ unsigned char sm[];
    const u32 smb = smem_u32(sm);
    const int tid = threadIdx.x, w = tid >> 5, l = tid & 31;
    const int row0 = blockIdx.x * 16;

    // ---- load agg [16 x 64] f32 -> fp16 tile A0 ----
    for (int i = tid; i < 512; i += 256) {
        int rr = i >> 5, cp = i & 31;
        float2 v = *(const float2*)&g_AGG[(row0 + rr) * 64 + cp * 2];
        *(u32*)(sm + NOFF_A0 + rr * N_STRIDE + cp * 4) = pk_h2(v.y, v.x);
    }
    __syncthreads();

    const u32 arow_base = smb + (l & 15) * N_STRIDE + ((l >> 4) * 8) * 2;
    const int ra = l >> 2, cshift = (l & 3) * 2;

    // ---- layer 1: K=64 (4 ksteps), N=256, warp w -> ntiles w*4..w*4+3 ----
    {
        float c[4][4];
#pragma unroll
        for (int n = 0; n < 4; ++n)
#pragma unroll
            for (int q = 0; q < 4; ++q) c[n][q] = 0.f;
        const u32 arow = arow_base + NOFF_A0;
        uint2 Bp[4];
#pragma unroll
        for (int n = 0; n < 4; ++n) Bp[n] = __ldg(&g_O1f[(w * 4 + n) * 32 + l]);
#pragma unroll
        for (int t = 0; t < 4; ++t) {
            u32 a0, a1, a2, a3;
            ldmatrix_x4(a0, a1, a2, a3, arow + t * 32);
            uint2 Bn[4];
            if (t < 3) {
#pragma unroll
                for (int n = 0; n < 4; ++n)
                    Bn[n] = __ldg(&g_O1f[((t + 1) * 32 + w * 4 + n) * 32 + l]);
            }
#pragma unroll
            for (int n = 0; n < 4; ++n) hmma(c[n], a0, a1, a2, a3, Bp[n].x, Bp[n].y);
#pragma unroll
            for (int n = 0; n < 4; ++n) Bp[n] = Bn[n];
        }
        __syncthreads();
#pragma unroll
        for (int n = 0; n < 4; ++n) {
            int col = w * 32 + n * 8 + cshift;
            float bb0 = __ldg(&o1b[col]), bb1 = __ldg(&o1b[col + 1]);
            *(u32*)(sm + NOFF_A1 + ra * N_STRIDE + col * 2) =
                pk_h2(fmaxf(c[n][1] + bb1, 0.f), fmaxf(c[n][0] + bb0, 0.f));
            *(u32*)(sm + NOFF_A1 + (ra + 8) * N_STRIDE + col * 2) =
                pk_h2(fmaxf(c[n][3] + bb1, 0.f), fmaxf(c[n][2] + bb0, 0.f));
        }
    }
    __syncthreads();

    // ---- layer 2: K=256 (16 ksteps), N=256 ----
    {
        float c[4][4];
#pragma unroll
        for (int n = 0; n < 4; ++n)
#pragma unroll
            for (int q = 0; q < 4; ++q) c[n][q] = 0.f;
        const u32 arow = arow_base + NOFF_A1;
        uint2 Bp[4];
#pragma unroll
        for (int n = 0; n < 4; ++n) Bp[n] = __ldg(&g_O2f[(w * 4 + n) * 32 + l]);
#pragma unroll 4
        for (int t = 0; t < 16; ++t) {
            u32 a0, a1, a2, a3;
            ldmatrix_x4(a0, a1, a2, a3, arow + t * 32);
            uint2 Bn[4];
            if (t < 15) {
#pragma unroll
                for (int n = 0; n < 4; ++n)
                    Bn[n] = __ldg(&g_O2f[((t + 1) * 32 + w * 4 + n) * 32 + l]);
            }
#pragma unroll
            for (int n = 0; n < 4; ++n) hmma(c[n], a0, a1, a2, a3, Bp[n].x, Bp[n].y);
#pragma unroll
            for (int n = 0; n < 4; ++n) Bp[n] = Bn[n];
        }
        __syncthreads();
#pragma unroll
        for (int n = 0; n < 4; ++n) {
            int col = w * 32 + n * 8 + cshift;
            float bb0 = __ldg(&o2b[col]), bb1 = __ldg(&o2b[col + 1]);
            *(u32*)(sm + NOFF_A0 + ra * N_STRIDE + col * 2) =
                pk_h2(fmaxf(c[n][1] + bb1, 0.f), fmaxf(c[n][0] + bb0, 0.f));
            *(u32*)(sm + NOFF_A0 + (ra + 8) * N_STRIDE + col * 2) =
                pk_h2(fmaxf(c[n][3] + bb1, 0.f), fmaxf(c[n][2] + bb0, 0.f));
        }
    }
    __syncthreads();

    // ---- layer 3: K=256 (16 ksteps), N=64; warp w -> cols w*8..w*8+7 ----
    {
        float c[4];
#pragma unroll
        for (int q = 0; q < 4; ++q) c[q] = 0.f;
        const u32 arow = arow_base + NOFF_A0;
        uint2 Bp = __ldg(&g_O3f[(w)*32 + l]);
#pragma unroll 4
        for (int t = 0; t < 16; ++t) {
            u32 a0, a1, a2, a3;
            ldmatrix_x4(a0, a1, a2, a3, arow + t * 32);
            uint2 Bn;
            if (t < 15) Bn = __ldg(&g_O3f[((t + 1) * 8 + w) * 32 + l]);
            hmma(c, a0, a1, a2, a3, Bp.x, Bp.y);
            Bp = Bn;
        }
        int col = w * 8 + cshift;
        float bb0 = __ldg(&o3b[col]), bb1 = __ldg(&o3b[col + 1]);
        *(float2*)&out[(row0 + ra) * 64 + col] = make_float2(c[0] + bb0, c[1] + bb1);
        *(float2*)&out[(row0 + ra + 8) * 64 + col] = make_float2(c[2] + bb0, c[3] + bb1);
    }
}

// ---------------- launch ----------------
extern "C" void kernel_launch(void* const* d_in, const int* in_sizes, int n_in,
                              void* d_out, int out_size) {
    const float* inputs = (const float*)d_in[0];
    const float* rel_types = (const float*)d_in[3];
    const float* W1 = (const float*)d_in[4];
    const float* b1 = (const float*)d_in[5];
    const float* W2 = (const float*)d_in[6];
    const float* b2 = (const float*)d_in[7];
    const float* O1 = (const float*)d_in[8];
    const float* o1b = (const float*)d_in[9];
    const float* O2 = (const float*)d_in[10];
    const float* o2b = (const float*)d_in[11];
    const float* O3 = (const float*)d_in[12];
    const float* o3b = (const float*)d_in[13];
    float* out = (float*)d_out;

    cudaFuncSetAttribute(edge_kernel, cudaFuncAttributeMaxDynamicSharedMemorySize, SMEM_EDGE);
    cudaFuncSetAttribute(node_kernel, cudaFuncAttributeMaxDynamicSharedMemorySize, SMEM_NODE);
    prep_kernel<<<160, 256>>>(W1, W2, O1, O2, O3);
    h1_kernel<<<BATCH * NNODE, 256>>>(inputs, b1);
    edge_kernel<<<BATCH * 64, 512, SMEM_EDGE>>>(rel_types, b2);
    node_kernel<<<256, 256, SMEM_NODE>>>(o1b, o2b, o3b, out);
}

// round 17
// speedup vs baseline: 1.1105x; 1.1105x over previous
#include <cuda_runtime.h>
#include <cuda_fp16.h>
#include <cstdint>

#define BATCH 32
#define NNODE 128
#define EDGES (NNODE * (NNODE - 1))

typedef unsigned long long ull;
typedef uint32_t u32;

// ---------------- static device scratch ----------------
__device__ float g_W1t[128 * 256];            // W1t[i*256+o] = W1[o,i]
__device__ uint4 g_Bp[16 * 4 * 32];           // W2 B-frags PAIRED: [kstep][ntile-pair][lane]
__device__ uint2 g_O1f[4 * 32 * 32];          // O1  B-frags (K=64,  N=256)
__device__ uint2 g_O2f[16 * 32 * 32];         // O2  B-frags (K=256, N=256)
__device__ uint2 g_O3f[16 * 8 * 32];          // O3  B-frags (K=256, N=64)
__device__ u32 g_H1s16[BATCH * NNODE * 128];  // fp16x2 sender-half
__device__ u32 g_H1r16[BATCH * NNODE * 128];  // fp16x2 recv-half (+b1)
__device__ float g_AGG[BATCH * NNODE * 64];

// ---------------- helpers ----------------
__device__ __forceinline__ u32 smem_u32(const void* p) {
    u32 a;
    asm("{ .reg .u64 t; cvta.to.shared.u64 t, %1; cvt.u32.u64 %0, t; }" : "=r"(a) : "l"(p));
    return a;
}
__device__ __forceinline__ u32 pk_h2(float hi_val, float lo_val) {
    u32 d; asm("cvt.rn.f16x2.f32 %0, %1, %2;" : "=r"(d) : "f"(hi_val), "f"(lo_val));
    return d;
}
__device__ __forceinline__ u32 frelu2(u32 hs, u32 hr) {
    u32 d;
    asm("fma.rn.relu.f16x2 %0, %1, %2, %3;" : "=r"(d) : "r"(hs), "r"(0x3C003C00u), "r"(hr));
    return d;
}
__device__ __forceinline__ void ldmatrix_x4(u32& a0, u32& a1, u32& a2, u32& a3, u32 addr) {
    asm volatile("ldmatrix.sync.aligned.m8n8.x4.shared.b16 {%0,%1,%2,%3}, [%4];"
                 : "=r"(a0), "=r"(a1), "=r"(a2), "=r"(a3) : "r"(addr));
}
__device__ __forceinline__ void hmma(float* c, u32 a0, u32 a1, u32 a2, u32 a3, u32 b0, u32 b1) {
    asm volatile(
        "mma.sync.aligned.m16n8k16.row.col.f32.f16.f16.f32 "
        "{%0,%1,%2,%3}, {%4,%5,%6,%7}, {%8,%9}, {%0,%1,%2,%3};"
        : "+f"(c[0]), "+f"(c[1]), "+f"(c[2]), "+f"(c[3])
        : "r"(a0), "r"(a1), "r"(a2), "r"(a3), "r"(b0), "r"(b1));
}
// build one B-fragment uint2 for row-major weight W[N][K]
__device__ __forceinline__ uint2 mk_bfrag(const float* W, int K, int t, int nt, int l) {
    int k0 = t * 16 + (l & 3) * 2;
    int col = nt * 8 + (l >> 2);
    __half h0 = __float2half_rn(W[col * K + k0]);
    __half h1 = __float2half_rn(W[col * K + k0 + 1]);
    __half h8 = __float2half_rn(W[col * K + k0 + 8]);
    __half h9 = __float2half_rn(W[col * K + k0 + 9]);
    uint2 o;
    o.x = (u32)__half_as_ushort(h0) | ((u32)__half_as_ushort(h1) << 16);
    o.y = (u32)__half_as_ushort(h8) | ((u32)__half_as_ushort(h9) << 16);
    return o;
}

// ---------------- prep: W1 transpose + all mma B-fragments ----------------
__global__ void prep_kernel(const float* __restrict__ W1, const float* __restrict__ W2,
                            const float* __restrict__ O1, const float* __restrict__ O2,
                            const float* __restrict__ O3) {
    const int total = 32768 + 2048 + 4096 + 16384 + 4096;
    for (int t0 = blockIdx.x * blockDim.x + threadIdx.x; t0 < total;
         t0 += gridDim.x * blockDim.x) {
        int x = t0;
        if (x < 32768) {
            int i = x >> 8, o = x & 255;
            g_W1t[x] = W1[o * 128 + i];
        } else if ((x -= 32768) < 2048) {      // W2 paired frags: 16 ksteps x 4 pairs
            int t = x >> 7, np = (x >> 5) & 3, l = x & 31;
            uint2 e0 = mk_bfrag(W2, 256, t, 2 * np, l);
            uint2 e1 = mk_bfrag(W2, 256, t, 2 * np + 1, l);
            g_Bp[x] = make_uint4(e0.x, e0.y, e1.x, e1.y);
        } else if ((x -= 2048) < 4096) {       // O1 frags: 4 ksteps x 32 ntiles
            int t = x >> 10, nt = (x >> 5) & 31, l = x & 31;
            g_O1f[x] = mk_bfrag(O1, 64, t, nt, l);
        } else if ((x -= 4096) < 16384) {      // O2 frags: 16 x 32
            int t = x >> 10, nt = (x >> 5) & 31, l = x & 31;
            g_O2f[x] = mk_bfrag(O2, 256, t, nt, l);
        } else {                               // O3 frags: 16 x 8
            x -= 16384;
            int t = x >> 8, nt = (x >> 5) & 7, l = x & 31;
            g_O3f[x] = mk_bfrag(O3, 256, t, nt, l);
        }
    }
}

// ---------------- h1: 4 nodes/CTA, weight-register reuse ----------------
// Thread (u = tid&127 output pair, half = tid>>7 sender/recv). Each loaded W1
// float2 feeds the FMAs of 4 rows. Per-row fma order identical to the 1-row
// version -> bit-identical H1 values.
__global__ void __launch_bounds__(256) h1_kernel(const float* __restrict__ inp,
                                                 const float* __restrict__ b1) {
    const int row0 = blockIdx.x * 4;
    const int tid = threadIdx.x;
    const int u = tid & 127, half = tid >> 7;
    __shared__ float xs[4][64];
    xs[tid >> 6][tid & 63] = inp[(row0 + (tid >> 6)) * 64 + (tid & 63)];
    __syncthreads();
    float bb0 = half ? b1[2 * u] : 0.f;
    float bb1 = half ? b1[2 * u + 1] : 0.f;
    float v0[4], v1[4];
#pragma unroll
    for (int rr = 0; rr < 4; ++rr) { v0[rr] = bb0; v1[rr] = bb1; }
    const float* wb = &g_W1t[half * 64 * 256 + 2 * u];
#pragma unroll 8
    for (int i = 0; i < 64; ++i) {
        float2 w = *(const float2*)(wb + i * 256);
#pragma unroll
        for (int rr = 0; rr < 4; ++rr) {
            float x = xs[rr][i];
            v0[rr] = fmaf(x, w.x, v0[rr]);
            v1[rr] = fmaf(x, w.y, v1[rr]);
        }
    }
#pragma unroll
    for (int rr = 0; rr < 4; ++rr) {
        u32 p = pk_h2(v1[rr], v0[rr]);
        if (half) g_H1r16[(row0 + rr) * 128 + u] = p;
        else      g_H1s16[(row0 + rr) * 128 + u] = p;
    }
}

// ---------------- edge kernel: warp-autonomous HMMA GEMM, two-pass ntiles ----------------
// One CTA per (b,r). Warp w stages its own 16 A-rows (edges 16w..16w+15, K=256,
// 528B stride), then runs the 16-kstep loop TWICE (ntile pairs {0,1} then {2,3}):
// peak regs ~60 (16 acc + 16 prefetch) so __launch_bounds__(256,3) cannot spill.
// Per-output k-accumulation order identical to the single-pass version.
#define A_STRIDE 528
#define OFF_A 0                  // 128*528 = 67584
#define OFF_RED 67584            // 8 warps x 68 floats = 2176
#define SMEM_EDGE 69760

__global__ void __launch_bounds__(256, 3) edge_kernel(const float* __restrict__ rt,
                                                      const float* __restrict__ b2) {
    extern __shared__ unsigned char sm[];
    const u32 smb = smem_u32(sm);
    const int r = blockIdx.x & 127, b = blockIdx.x >> 7;
    const int tid = threadIdx.x, w = tid >> 5, l = tid & 31;
    float* red = (float*)(sm + OFF_RED);

    // per-warp rt weights: lane l<16 holds rt-sum for edge w*16+l
    float rtv = 0.f;
    {
        int e0 = w * 16 + l;
        if (l < 16 && e0 < 127) {
            const float* q = rt + ((size_t)(b * EDGES + r * 127 + e0)) * 2;
            rtv = q[0] + q[1];
        }
    }

    const u32* h1s = &g_H1s16[b * NNODE * 128];
    const u32* h1r = &g_H1r16[(b * NNODE + r) * 128];

    // ---- stage own 16 rows: fused add+relu fp16x2, coalesced uint4 ----
    uint4 hr4 = *(const uint4*)&h1r[l * 4];
    const int rowb = OFF_A + (w * 16) * A_STRIDE + l * 16;
#pragma unroll
    for (int i = 0; i < 16; ++i) {
        int e = w * 16 + i;
        uint4 v = make_uint4(0u, 0u, 0u, 0u);
        if (e < 127) {
            int s = e + (e >= r);
            uint4 hs4 = *(const uint4*)&h1s[s * 128 + l * 4];
            v.x = frelu2(hs4.x, hr4.x);
            v.y = frelu2(hs4.y, hr4.y);
            v.z = frelu2(hs4.z, hr4.z);
            v.w = frelu2(hs4.w, hr4.w);
        }
        *(uint4*)(sm + rowb + i * A_STRIDE) = v;
    }
    __syncwarp();

    const u32 arow = smb + OFF_A + (w * 16 + (l & 15)) * A_STRIDE + (l >> 4) * 16;
    float rt0 = __shfl_sync(0xffffffffu, rtv, l >> 2);
    float rt1 = __shfl_sync(0xffffffffu, rtv, 8 + (l >> 2));

#pragma unroll
    for (int pass = 0; pass < 2; ++pass) {
        // ---- mma: 16 k-steps x 4 n-tiles (pairs pass*2, pass*2+1) ----
        float c[4][4];
#pragma unroll
        for (int n = 0; n < 4; ++n)
#pragma unroll
            for (int q = 0; q < 4; ++q) c[n][q] = 0.f;

        uint4 Bp[2];
#pragma unroll
        for (int np = 0; np < 2; ++np)
            Bp[np] = __ldg(&g_Bp[(pass * 2 + np) * 32 + l]);
#pragma unroll
        for (int t = 0; t < 16; ++t) {
            u32 a0, a1, a2, a3;
            ldmatrix_x4(a0, a1, a2, a3, arow + t * 32);
            uint4 Bn[2];
            if (t < 15) {
#pragma unroll
                for (int np = 0; np < 2; ++np)
                    Bn[np] = __ldg(&g_Bp[((t + 1) * 4 + pass * 2 + np) * 32 + l]);
            }
#pragma unroll
            for (int np = 0; np < 2; ++np) {
                hmma(c[2 * np], a0, a1, a2, a3, Bp[np].x, Bp[np].y);
                hmma(c[2 * np + 1], a0, a1, a2, a3, Bp[np].z, Bp[np].w);
            }
#pragma unroll
            for (int np = 0; np < 2; ++np) Bp[np] = Bn[np];
        }

        // ---- epilogue for this pass's 4 ntiles ----
#pragma unroll
        for (int n4 = 0; n4 < 4; ++n4) {
            int n0 = (pass * 4 + n4) * 8 + (l & 3) * 2;
            float bb0 = __ldg(&b2[n0]), bb1 = __ldg(&b2[n0 + 1]);
            float u0 = fmaxf(c[n4][0] + bb0, 0.f) * rt0 + fmaxf(c[n4][2] + bb0, 0.f) * rt1;
            float u1 = fmaxf(c[n4][1] + bb1, 0.f) * rt0 + fmaxf(c[n4][3] + bb1, 0.f) * rt1;
#pragma unroll
            for (int off = 4; off < 32; off <<= 1) {
                u0 += __shfl_xor_sync(0xffffffffu, u0, off);
                u1 += __shfl_xor_sync(0xffffffffu, u1, off);
            }
            if (l < 4) {
                red[w * 68 + n0] = u0;
                red[w * 68 + n0 + 1] = u1;
            }
        }
    }
    __syncthreads();
    if (tid < 64) {
        float a = 0.f;
#pragma unroll
        for (int ww = 0; ww < 8; ++ww) a += red[ww * 68 + tid];
        g_AGG[(b * NNODE + r) * 64 + tid] = a;
    }
}

// ---------------- node kernel: HMMA MLP 64 -> 256 -> 256 -> 64 ----------------
#define N_STRIDE 528
#define NOFF_A0 0
#define NOFF_A1 8448
#define SMEM_NODE 16896

__global__ void __launch_bounds__(256) node_kernel(const float* __restrict__ o1b,
                                                   const float* __restrict__ o2b,
                                                   const float* __restrict__ o3b,
                                                   float* __restrict__ out) {
    extern __shared__ unsigned char sm[];
    const u32 smb = smem_u32(sm);
    const int tid = threadIdx.x, w = tid >> 5, l = tid & 31;
    const int row0 = blockIdx.x * 16;

    // ---- load agg [16 x 64] f32 -> fp16 tile A0 ----
    for (int i = tid; i < 512; i += 256) {
        int rr = i >> 5, cp = i & 31;
        float2 v = *(const float2*)&g_AGG[(row0 + rr) * 64 + cp * 2];
        *(u32*)(sm + NOFF_A0 + rr * N_STRIDE + cp * 4) = pk_h2(v.y, v.x);
    }
    __syncthreads();

    const u32 arow_base = smb + (l & 15) * N_STRIDE + ((l >> 4) * 8) * 2;
    const int ra = l >> 2, cshift = (l & 3) * 2;

    // ---- layer 1: K=64 (4 ksteps), N=256, warp w -> ntiles w*4..w*4+3 ----
    {
        float c[4][4];
#pragma unroll
        for (int n = 0; n < 4; ++n)
#pragma unroll
            for (int q = 0; q < 4; ++q) c[n][q] = 0.f;
        const u32 arow = arow_base + NOFF_A0;
        uint2 Bp[4];
#pragma unroll
        for (int n = 0; n < 4; ++n) Bp[n] = __ldg(&g_O1f[(w * 4 + n) * 32 + l]);
#pragma unroll
        for (int t = 0; t < 4; ++t) {
            u32 a0, a1, a2, a3;
            ldmatrix_x4(a0, a1, a2, a3, arow + t * 32);
            uint2 Bn[4];
            if (t < 3) {
#pragma unroll
                for (int n = 0; n < 4; ++n)
                    Bn[n] = __ldg(&g_O1f[((t + 1) * 32 + w * 4 + n) * 32 + l]);
            }
#pragma unroll
            for (int n = 0; n < 4; ++n) hmma(c[n], a0, a1, a2, a3, Bp[n].x, Bp[n].y);
#pragma unroll
            for (int n = 0; n < 4; ++n) Bp[n] = Bn[n];
        }
        __syncthreads();
#pragma unroll
        for (int n = 0; n < 4; ++n) {
            int col = w * 32 + n * 8 + cshift;
            float bb0 = __ldg(&o1b[col]), bb1 = __ldg(&o1b[col + 1]);
            *(u32*)(sm + NOFF_A1 + ra * N_STRIDE + col * 2) =
                pk_h2(fmaxf(c[n][1] + bb1, 0.f), fmaxf(c[n][0] + bb0, 0.f));
            *(u32*)(sm + NOFF_A1 + (ra + 8) * N_STRIDE + col * 2) =
                pk_h2(fmaxf(c[n][3] + bb1, 0.f), fmaxf(c[n][2] + bb0, 0.f));
        }
    }
    __syncthreads();

    // ---- layer 2: K=256 (16 ksteps), N=256 ----
    {
        float c[4][4];
#pragma unroll
        for (int n = 0; n < 4; ++n)
#pragma unroll
            for (int q = 0; q < 4; ++q) c[n][q] = 0.f;
        const u32 arow = arow_base + NOFF_A1;
        uint2 Bp[4];
#pragma unroll
        for (int n = 0; n < 4; ++n) Bp[n] = __ldg(&g_O2f[(w * 4 + n) * 32 + l]);
#pragma unroll 4
        for (int t = 0; t < 16; ++t) {
            u32 a0, a1, a2, a3;
            ldmatrix_x4(a0, a1, a2, a3, arow + t * 32);
            uint2 Bn[4];
            if (t < 15) {
#pragma unroll
                for (int n = 0; n < 4; ++n)
                    Bn[n] = __ldg(&g_O2f[((t + 1) * 32 + w * 4 + n) * 32 + l]);
            }
#pragma unroll
            for (int n = 0; n < 4; ++n) hmma(c[n], a0, a1, a2, a3, Bp[n].x, Bp[n].y);
#pragma unroll
            for (int n = 0; n < 4; ++n) Bp[n] = Bn[n];
        }
        __syncthreads();
#pragma unroll
        for (int n = 0; n < 4; ++n) {
            int col = w * 32 + n * 8 + cshift;
            float bb0 = __ldg(&o2b[col]), bb1 = __ldg(&o2b[col + 1]);
            *(u32*)(sm + NOFF_A0 + ra * N_STRIDE + col * 2) =
                pk_h2(fmaxf(c[n][1] + bb1, 0.f), fmaxf(c[n][0] + bb0, 0.f));
            *(u32*)(sm + NOFF_A0 + (ra + 8) * N_STRIDE + col * 2) =
                pk_h2(fmaxf(c[n][3] + bb1, 0.f), fmaxf(c[n][2] + bb0, 0.f));
        }
    }
    __syncthreads();

    // ---- layer 3: K=256 (16 ksteps), N=64; warp w -> cols w*8..w*8+7 ----
    {
        float c[4];
#pragma unroll
        for (int q = 0; q < 4; ++q) c[q] = 0.f;
        const u32 arow = arow_base + NOFF_A0;
        uint2 Bp = __ldg(&g_O3f[(w)*32 + l]);
#pragma unroll 4
        for (int t = 0; t < 16; ++t) {
            u32 a0, a1, a2, a3;
            ldmatrix_x4(a0, a1, a2, a3, arow + t * 32);
            uint2 Bn;
            if (t < 15) Bn = __ldg(&g_O3f[((t + 1) * 8 + w) * 32 + l]);
            hmma(c, a0, a1, a2, a3, Bp.x, Bp.y);
            Bp = Bn;
        }
        int col = w * 8 + cshift;
        float bb0 = __ldg(&o3b[col]), bb1 = __ldg(&o3b[col + 1]);
        *(float2*)&out[(row0 + ra) * 64 + col] = make_float2(c[0] + bb0, c[1] + bb1);
        *(float2*)&out[(row0 + ra + 8) * 64 + col] = make_float2(c[2] + bb0, c[3] + bb1);
    }
}

// ---------------- launch ----------------
extern "C" void kernel_launch(void* const* d_in, const int* in_sizes, int n_in,
                              void* d_out, int out_size) {
    const float* inputs = (const float*)d_in[0];
    const float* rel_types = (const float*)d_in[3];
    const float* W1 = (const float*)d_in[4];
    const float* b1 = (const float*)d_in[5];
    const float* W2 = (const float*)d_in[6];
    const float* b2 = (const float*)d_in[7];
    const float* O1 = (const float*)d_in[8];
    const float* o1b = (const float*)d_in[9];
    const float* O2 = (const float*)d_in[10];
    const float* o2b = (const float*)d_in[11];
    const float* O3 = (const float*)d_in[12];
    const float* o3b = (const float*)d_in[13];
    float* out = (float*)d_out;

    cudaFuncSetAttribute(edge_kernel, cudaFuncAttributeMaxDynamicSharedMemorySize, SMEM_EDGE);
    cudaFuncSetAttribute(node_kernel, cudaFuncAttributeMaxDynamicSharedMemorySize, SMEM_NODE);
    prep_kernel<<<160, 256>>>(W1, W2, O1, O2, O3);
    h1_kernel<<<BATCH * NNODE / 4, 256>>>(inputs, b1);
    edge_kernel<<<BATCH * NNODE, 256, SMEM_EDGE>>>(rel_types, b2);
    node_kernel<<<256, 256, SMEM_NODE>>>(o1b, o2b, o3b, out);
}